// round 2
// baseline (speedup 1.0000x reference)
#include <cuda_runtime.h>
#include <math.h>

// Problem constants (fixed by the reference)
#define BB 4
#define TT 2048
#define DD 1024
#define HH 16
#define DK 64
#define MROWS (BB * TT)          // 8192

// Scratch (allocation-free rule: __device__ globals)
__device__ float g_qkv[(size_t)MROWS * 3 * DD];  // [8192][3072]  q|k|v
__device__ float g_y[(size_t)MROWS * DD];        // [8192][1024]

// ---------------------------------------------------------------------------
// GEMM: C[M,N] = A[M,K] @ B[N,K]^T + bias[N]   (both inputs K-major, "NT")
// 128x128 block, BK=16, 256 threads, 8x8 per thread.
// ---------------------------------------------------------------------------
__global__ __launch_bounds__(256)
void gemm_nt_bias(const float* __restrict__ A, const float* __restrict__ Bm,
                  const float* __restrict__ bias, float* __restrict__ C,
                  int M, int N, int K)
{
    __shared__ float As[16][128];
    __shared__ float Bs[16][128];

    const int tid = threadIdx.x;
    const int mb  = blockIdx.y * 128;
    const int nb  = blockIdx.x * 128;
    const int tr  = tid >> 4;   // 0..15
    const int tc  = tid & 15;   // 0..15

    float acc[8][8];
#pragma unroll
    for (int i = 0; i < 8; i++)
#pragma unroll
        for (int j = 0; j < 8; j++) acc[i][j] = 0.f;

    for (int k0 = 0; k0 < K; k0 += 16) {
#pragma unroll
        for (int it = 0; it < 2; it++) {
            int s   = tid + it * 256;          // 0..511 float4 slots
            int row = s >> 2;                  // 0..127
            int q   = (s & 3) * 4;             // k offset 0,4,8,12
            float4 a = *(const float4*)(A + (size_t)(mb + row) * K + k0 + q);
            As[q + 0][row] = a.x; As[q + 1][row] = a.y;
            As[q + 2][row] = a.z; As[q + 3][row] = a.w;
            float4 b = *(const float4*)(Bm + (size_t)(nb + row) * K + k0 + q);
            Bs[q + 0][row] = b.x; Bs[q + 1][row] = b.y;
            Bs[q + 2][row] = b.z; Bs[q + 3][row] = b.w;
        }
        __syncthreads();

#pragma unroll
        for (int k = 0; k < 16; k++) {
            float ra[8], rb[8];
            *(float4*)(ra)     = *(const float4*)(&As[k][tr * 8]);
            *(float4*)(ra + 4) = *(const float4*)(&As[k][tr * 8 + 4]);
            *(float4*)(rb)     = *(const float4*)(&Bs[k][tc * 8]);
            *(float4*)(rb + 4) = *(const float4*)(&Bs[k][tc * 8 + 4]);
#pragma unroll
            for (int i = 0; i < 8; i++)
#pragma unroll
                for (int j = 0; j < 8; j++)
                    acc[i][j] += ra[i] * rb[j];
        }
        __syncthreads();
    }

#pragma unroll
    for (int i = 0; i < 8; i++) {
        int row = mb + tr * 8 + i;
#pragma unroll
        for (int j = 0; j < 8; j += 4) {
            int col = nb + tc * 8 + j;
            float4 bv = *(const float4*)(bias + col);
            float4 o;
            o.x = acc[i][j + 0] + bv.x;
            o.y = acc[i][j + 1] + bv.y;
            o.z = acc[i][j + 2] + bv.z;
            o.w = acc[i][j + 3] + bv.w;
            *(float4*)(C + (size_t)row * N + col) = o;
        }
    }
}

// ---------------------------------------------------------------------------
// Flash attention (fp32, causal + key-pad mask).
// One block = 64 queries of one (b, h). 256 threads as 16x16; each thread
// owns a 4(q) x 4(k or d) register tile. K tiles of 64 streamed with online
// softmax. Smem tiles stored transposed with pad 65 (conflict mitigation).
// ---------------------------------------------------------------------------
#define PAD 65
#define ATT_SMEM ((3 * 64 * PAD + 64 * 64) * 4 + 64 * 4)

__global__ __launch_bounds__(256)
void attn_kernel(const float* __restrict__ qkv, const int* __restrict__ mask,
                 float* __restrict__ y)
{
    extern __shared__ float sm[];
    float* QsT = sm;                       // [64][65]  (d-major)
    float* KsT = sm + 64 * PAD;            // [64][65]  (d-major)
    float* PsT = sm + 2 * 64 * PAD;        // [64][65]  (k-major: PsT[j][q])
    float* Vs  = sm + 3 * 64 * PAD;        // [64][64]  (k rows, d cols)
    int*  padm = (int*)(sm + 3 * 64 * PAD + 64 * 64);  // [64]

    const int tid   = threadIdx.x;
    const int b     = blockIdx.z;
    const int hh    = blockIdx.y;
    const int qbase = blockIdx.x * 64;
    const int r4    = (tid >> 4) * 4;      // this thread's first q row (0..60)
    const int c4    = (tid & 15) * 4;      // this thread's first k/d col

    const size_t rs = 3 * DD;              // qkv row stride in floats

    // Load Q tile transposed: QsT[d][q]
    const float* qp = qkv + ((size_t)b * TT + qbase) * rs + hh * DK;
#pragma unroll
    for (int it = 0; it < 4; it++) {
        int s  = tid + it * 256;           // 0..1023 float4 slots
        int qq = s >> 4;                   // 0..63
        int dq = (s & 15) * 4;             // 0..60
        float4 v = *(const float4*)(qp + (size_t)qq * rs + dq);
        QsT[(dq + 0) * PAD + qq] = v.x;
        QsT[(dq + 1) * PAD + qq] = v.y;
        QsT[(dq + 2) * PAD + qq] = v.z;
        QsT[(dq + 3) * PAD + qq] = v.w;
    }

    float acc[4][4];
    float m_run[4], l_run[4];
#pragma unroll
    for (int i = 0; i < 4; i++) {
        m_run[i] = -INFINITY; l_run[i] = 0.f;
#pragma unroll
        for (int j = 0; j < 4; j++) acc[i][j] = 0.f;
    }

    const int ntiles = blockIdx.x + 1;     // causal: keys only up to diagonal
    for (int kt = 0; kt < ntiles; kt++) {
        const int j0 = kt * 64;
        __syncthreads();                   // protect KsT/Vs/PsT from prior iter

        const float* kp = qkv + ((size_t)b * TT + j0) * rs + DD + hh * DK;
        const float* vp = kp + DD;
#pragma unroll
        for (int it = 0; it < 4; it++) {
            int s  = tid + it * 256;
            int jj = s >> 4;
            int dq = (s & 15) * 4;
            float4 v = *(const float4*)(kp + (size_t)jj * rs + dq);
            KsT[(dq + 0) * PAD + jj] = v.x;
            KsT[(dq + 1) * PAD + jj] = v.y;
            KsT[(dq + 2) * PAD + jj] = v.z;
            KsT[(dq + 3) * PAD + jj] = v.w;
            float4 w = *(const float4*)(vp + (size_t)jj * rs + dq);
            *(float4*)(Vs + jj * 64 + dq) = w;
        }
        if (tid < 64) padm[tid] = mask[b * TT + j0 + tid];
        __syncthreads();

        // S = Q @ K^T  (4x4 per thread)
        float s4[4][4];
#pragma unroll
        for (int i = 0; i < 4; i++)
#pragma unroll
            for (int j = 0; j < 4; j++) s4[i][j] = 0.f;

#pragma unroll 8
        for (int d = 0; d < 64; d++) {
            float qr[4], kr[4];
#pragma unroll
            for (int i = 0; i < 4; i++) qr[i] = QsT[d * PAD + r4 + i];
#pragma unroll
            for (int j = 0; j < 4; j++) kr[j] = KsT[d * PAD + c4 + j];
#pragma unroll
            for (int i = 0; i < 4; i++)
#pragma unroll
                for (int j = 0; j < 4; j++)
                    s4[i][j] += qr[i] * kr[j];
        }

        // mask + scale (1/sqrt(64) = 0.125)
#pragma unroll
        for (int j = 0; j < 4; j++) {
            const int  jg = j0 + c4 + j;
            const bool pm = (padm[c4 + j] != 0);
#pragma unroll
            for (int i = 0; i < 4; i++) {
                const int qg = qbase + r4 + i;
                s4[i][j] = (pm && jg <= qg) ? s4[i][j] * 0.125f : -INFINITY;
            }
        }

        // online softmax per q row (reduction over the 16 lanes of a half-warp)
#pragma unroll
        for (int i = 0; i < 4; i++) {
            float mloc = fmaxf(fmaxf(s4[i][0], s4[i][1]),
                               fmaxf(s4[i][2], s4[i][3]));
#pragma unroll
            for (int off = 8; off >= 1; off >>= 1)
                mloc = fmaxf(mloc, __shfl_xor_sync(0xffffffffu, mloc, off));

            if (mloc > -INFINITY) {
                float mnew  = fmaxf(m_run[i], mloc);
                float alpha = __expf(m_run[i] - mnew);  // exp(-inf)=0 on first tile
                float psum  = 0.f;
#pragma unroll
                for (int j = 0; j < 4; j++) {
                    float p = __expf(s4[i][j] - mnew);
                    s4[i][j] = p;
                    psum += p;
                }
#pragma unroll
                for (int off = 8; off >= 1; off >>= 1)
                    psum += __shfl_xor_sync(0xffffffffu, psum, off);
                l_run[i] = l_run[i] * alpha + psum;
                m_run[i] = mnew;
#pragma unroll
                for (int j = 0; j < 4; j++) acc[i][j] *= alpha;
            } else {
#pragma unroll
                for (int j = 0; j < 4; j++) s4[i][j] = 0.f;  // fully masked row
            }
#pragma unroll
            for (int j = 0; j < 4; j++)
                PsT[(c4 + j) * PAD + r4 + i] = s4[i][j];
        }
        __syncthreads();

        // O += P @ V  (4x4 per thread)
#pragma unroll 4
        for (int jj = 0; jj < 64; jj++) {
            float pv[4];
#pragma unroll
            for (int i = 0; i < 4; i++) pv[i] = PsT[jj * PAD + r4 + i];
            float4 vf = *(const float4*)(Vs + jj * 64 + c4);
            acc[0][0] += pv[0] * vf.x; acc[0][1] += pv[0] * vf.y;
            acc[0][2] += pv[0] * vf.z; acc[0][3] += pv[0] * vf.w;
            acc[1][0] += pv[1] * vf.x; acc[1][1] += pv[1] * vf.y;
            acc[1][2] += pv[1] * vf.z; acc[1][3] += pv[1] * vf.w;
            acc[2][0] += pv[2] * vf.x; acc[2][1] += pv[2] * vf.y;
            acc[2][2] += pv[2] * vf.z; acc[2][3] += pv[2] * vf.w;
            acc[3][0] += pv[3] * vf.x; acc[3][1] += pv[3] * vf.y;
            acc[3][2] += pv[3] * vf.z; acc[3][3] += pv[3] * vf.w;
        }
    }

    // write y[b][t][h*64 + d] = O / l
#pragma unroll
    for (int i = 0; i < 4; i++) {
        float inv = (l_run[i] > 0.f) ? (1.0f / l_run[i]) : 0.f;
        int t = qbase + r4 + i;
        float4 o;
        o.x = acc[i][0] * inv; o.y = acc[i][1] * inv;
        o.z = acc[i][2] * inv; o.w = acc[i][3] * inv;
        *(float4*)(y + ((size_t)b * TT + t) * DD + hh * DK + c4) = o;
    }
}

// ---------------------------------------------------------------------------
extern "C" void kernel_launch(void* const* d_in, const int* in_sizes, int n_in,
                              void* d_out, int out_size)
{
    const float* x     = (const float*)d_in[0];
    const float* Wqkv  = (const float*)d_in[1];
    const float* bqkv  = (const float*)d_in[2];
    const float* Wproj = (const float*)d_in[3];
    const float* bproj = (const float*)d_in[4];
    const int*   mask  = (const int*)d_in[5];
    float* out = (float*)d_out;

    float *qkvp, *yp;
    cudaGetSymbolAddress((void**)&qkvp, g_qkv);
    cudaGetSymbolAddress((void**)&yp, g_y);

    cudaFuncSetAttribute(attn_kernel,
                         cudaFuncAttributeMaxDynamicSharedMemorySize, ATT_SMEM);

    // qkv = x @ Wqkv^T + bqkv   -> g_qkv [8192, 3072]
    gemm_nt_bias<<<dim3(3 * DD / 128, MROWS / 128), 256>>>(
        x, Wqkv, bqkv, qkvp, MROWS, 3 * DD, DD);

    // attention -> g_y [8192, 1024]
    attn_kernel<<<dim3(TT / 64, HH, BB), 256, ATT_SMEM>>>(qkvp, mask, yp);

    // out = y @ Wproj^T + bproj
    gemm_nt_bias<<<dim3(DD / 128, MROWS / 128), 256>>>(
        yp, Wproj, bproj, out, MROWS, DD, DD);
}

// round 7
// speedup vs baseline: 1.0067x; 1.0067x over previous
#include <cuda_runtime.h>
#include <cuda_bf16.h>
#include <cstdint>
#include <stdint.h>
#include <math.h>

// Problem constants (fixed by the reference)
#define BB 4
#define TT 2048
#define DD 1024
#define HH 16
#define DK 64
#define MROWS (BB * TT)          // 8192
#define KSPLIT (3 * DD)          // 3072 = split-K' for compensated bf16 GEMM

// Scratch (allocation-free rule: __device__ globals)
__device__ float         g_qkv[(size_t)MROWS * 3 * DD];     // [8192][3072] q|k|v fp32
__device__ float         g_y[(size_t)MROWS * DD];           // [8192][1024] fp32
__device__ __nv_bfloat16 g_xp[(size_t)MROWS * KSPLIT];      // x  split  (hi|lo|hi)
__device__ __nv_bfloat16 g_wqkvp[(size_t)(3 * DD) * KSPLIT];// Wqkv split (hi|hi|lo)
__device__ __nv_bfloat16 g_yp[(size_t)MROWS * KSPLIT];      // y  split  (hi|lo|hi)
__device__ __nv_bfloat16 g_wprojp[(size_t)DD * KSPLIT];     // Wproj split (hi|hi|lo)

// ---------------------------------------------------------------------------
// helpers (all baseline PTX — compiles on compute_103)
// ---------------------------------------------------------------------------
__device__ __forceinline__ uint32_t smem_u32(const void* p) {
    uint32_t a;
    asm("{ .reg .u64 t; cvta.to.shared.u64 t, %1; cvt.u32.u64 %0, t; }"
        : "=r"(a) : "l"(p));
    return a;
}
__device__ __forceinline__ void cp16(uint32_t saddr, const void* gaddr) {
    asm volatile("cp.async.cg.shared.global [%0], [%1], 16;"
                 :: "r"(saddr), "l"(gaddr) : "memory");
}
__device__ __forceinline__ void cp_commit() {
    asm volatile("cp.async.commit_group;" ::: "memory");
}
template <int N>
__device__ __forceinline__ void cp_wait() {
    asm volatile("cp.async.wait_group %0;" :: "n"(N) : "memory");
}
__device__ __forceinline__ void ldsm_x4(uint32_t* r, uint32_t addr) {
    asm volatile("ldmatrix.sync.aligned.m8n8.x4.shared.b16 {%0,%1,%2,%3}, [%4];"
                 : "=r"(r[0]), "=r"(r[1]), "=r"(r[2]), "=r"(r[3]) : "r"(addr));
}
__device__ __forceinline__ void mma_bf16(float* c, const uint32_t* a,
                                         const uint32_t* b) {
    asm volatile(
        "mma.sync.aligned.m16n8k16.row.col.f32.bf16.bf16.f32 "
        "{%0,%1,%2,%3}, {%4,%5,%6,%7}, {%8,%9}, {%0,%1,%2,%3};"
        : "+f"(c[0]), "+f"(c[1]), "+f"(c[2]), "+f"(c[3])
        : "r"(a[0]), "r"(a[1]), "r"(a[2]), "r"(a[3]), "r"(b[0]), "r"(b[1]));
}
__device__ __forceinline__ uint32_t sw128(uint32_t bo) {
    return bo ^ ((bo >> 3) & 0x70);
}

#define GEMM_SMEM 65536   // 2 x (16KB A + 16KB B)

// ---------------------------------------------------------------------------
// Tensor-core GEMM via mma.sync: C[M,N] = A[M,K] @ B[N,K]^T + bias[N]
// A, B bf16 K-major; C fp32. 128x128 CTA tile, 256 threads (8 warps, 2x4),
// warp tile 64x32, K-chunks of 64, cp.async double buffer.
// ---------------------------------------------------------------------------
__global__ __launch_bounds__(256)
void gemm_bf16_mma(const __nv_bfloat16* __restrict__ A,
                   const __nv_bfloat16* __restrict__ B,
                   const float* __restrict__ bias, float* __restrict__ C,
                   int M, int N, int K)
{
    extern __shared__ char smc[];
    const uint32_t sb = smem_u32(smc);
    const int tid  = threadIdx.x;
    const int wid  = tid >> 5;
    const int lane = tid & 31;
    const int nb   = blockIdx.x * 128;
    const int mb   = blockIdx.y * 128;
    const int mw   = (wid >> 2) * 64;   // warp M offset in tile
    const int nw   = (wid & 3) * 32;    // warp N offset in tile

    const uint32_t sA = sb;             // [2][128][128B]
    const uint32_t sB = sb + 32768;     // [2][128][128B]

    float acc[4][4][4];                 // [mt][nt][frag]
#pragma unroll
    for (int mt = 0; mt < 4; mt++)
#pragma unroll
        for (int nt = 0; nt < 4; nt++)
#pragma unroll
            for (int q = 0; q < 4; q++) acc[mt][nt][q] = 0.f;

    // per-thread load slots: 4 x 16B for A, same for B
    const int lrow = tid >> 3;          // 0..31  (+32 per i)
    const int lci  = tid & 7;           // 16B col
    const uint32_t lsw = sw128((uint32_t)(lrow * 128 + lci * 16));

    const int nch = K >> 6;

    // prologue: issue chunk 0 into buffer 0
    {
        const __nv_bfloat16* Ap = A + (size_t)mb * K;
        const __nv_bfloat16* Bp = B + (size_t)nb * K;
#pragma unroll
        for (int i = 0; i < 4; i++) {
            const uint32_t so = lsw + i * 4096;   // +32 rows = +4096B (swizzle row-local)
            cp16(sA + so, Ap + (size_t)(lrow + i * 32) * K + lci * 8);
            cp16(sB + so, Bp + (size_t)(lrow + i * 32) * K + lci * 8);
        }
        cp_commit();
    }

    for (int c = 0; c < nch; c++) {
        const int s = c & 1;
        if (c + 1 < nch) {
            const int k0 = (c + 1) << 6;
            const __nv_bfloat16* Ap = A + (size_t)mb * K + k0;
            const __nv_bfloat16* Bp = B + (size_t)nb * K + k0;
            const uint32_t sbuf = (s ^ 1) * 16384;
#pragma unroll
            for (int i = 0; i < 4; i++) {
                const uint32_t so = sbuf + lsw + i * 4096;
                cp16(sA + so, Ap + (size_t)(lrow + i * 32) * K + lci * 8);
                cp16(sB + so, Bp + (size_t)(lrow + i * 32) * K + lci * 8);
            }
            cp_commit();
            cp_wait<1>();
        } else {
            cp_wait<0>();
        }
        __syncthreads();

        const uint32_t baseA = sA + s * 16384;
        const uint32_t baseB = sB + s * 16384;
#pragma unroll
        for (int ks = 0; ks < 4; ks++) {
            uint32_t af[4][4];
#pragma unroll
            for (int mt = 0; mt < 4; mt++) {
                const int row = mw + mt * 16 + (lane & 15);
                const uint32_t bo =
                    (uint32_t)(row * 128 + ks * 32 + ((lane >> 4) & 1) * 16);
                ldsm_x4(af[mt], baseA + sw128(bo));
            }
            uint32_t bf[4][2];
#pragma unroll
            for (int nt2 = 0; nt2 < 2; nt2++) {
                const int row = nw + nt2 * 16 + ((lane >> 4) << 3) + (lane & 7);
                const uint32_t bo =
                    (uint32_t)(row * 128 + ks * 32 + ((lane >> 3) & 1) * 16);
                uint32_t t[4];
                ldsm_x4(t, baseB + sw128(bo));
                bf[nt2 * 2 + 0][0] = t[0]; bf[nt2 * 2 + 0][1] = t[1];
                bf[nt2 * 2 + 1][0] = t[2]; bf[nt2 * 2 + 1][1] = t[3];
            }
#pragma unroll
            for (int mt = 0; mt < 4; mt++)
#pragma unroll
                for (int nt = 0; nt < 4; nt++)
                    mma_bf16(acc[mt][nt], af[mt], bf[nt]);
        }
        __syncthreads();
    }

    // epilogue: c-frag thread mapping — rows lane/4 (+8), cols (lane%4)*2 (+1)
    const int r0 = mb + mw + (lane >> 2);
    const int c0 = nb + nw + (lane & 3) * 2;
#pragma unroll
    for (int mt = 0; mt < 4; mt++) {
#pragma unroll
        for (int nt = 0; nt < 4; nt++) {
            const int col = c0 + nt * 8;
            const float bx = bias[col], by = bias[col + 1];
            float2 v0 = make_float2(acc[mt][nt][0] + bx, acc[mt][nt][1] + by);
            float2 v1 = make_float2(acc[mt][nt][2] + bx, acc[mt][nt][3] + by);
            *(float2*)(C + (size_t)(r0 + mt * 16) * N + col)     = v0;
            *(float2*)(C + (size_t)(r0 + mt * 16 + 8) * N + col) = v1;
        }
    }
}

// ---------------------------------------------------------------------------
// Split fp32 -> compensated bf16 triple along K.
// type 0 (A operand): (hi | lo | hi)   type 1 (B operand): (hi | hi | lo)
// ---------------------------------------------------------------------------
__global__ __launch_bounds__(256)
void split_hilo(const float* __restrict__ in, __nv_bfloat16* __restrict__ out,
                int total, int type)
{
    int idx = blockIdx.x * 256 + threadIdx.x;
    if (idx >= total) return;
    const int r = idx >> 10;
    const int k = idx & 1023;
    const float x = in[idx];
    const __nv_bfloat16 h = __float2bfloat16(x);
    const __nv_bfloat16 l = __float2bfloat16(x - __bfloat162float(h));
    const size_t o = (size_t)r * KSPLIT + k;
    if (type == 0) { out[o] = h; out[o + 1024] = l; out[o + 2048] = h; }
    else           { out[o] = h; out[o + 1024] = h; out[o + 2048] = l; }
}

// ---------------------------------------------------------------------------
// Flash attention (fp32, causal + key-pad mask). Unchanged from R1.
// ---------------------------------------------------------------------------
#define PAD 65
#define ATT_SMEM ((3 * 64 * PAD + 64 * 64) * 4 + 64 * 4)

__global__ __launch_bounds__(256)
void attn_kernel(const float* __restrict__ qkv, const int* __restrict__ mask,
                 float* __restrict__ y)
{
    extern __shared__ float sm[];
    float* QsT = sm;
    float* KsT = sm + 64 * PAD;
    float* PsT = sm + 2 * 64 * PAD;
    float* Vs  = sm + 3 * 64 * PAD;
    int*  padm = (int*)(sm + 3 * 64 * PAD + 64 * 64);

    const int tid   = threadIdx.x;
    const int b     = blockIdx.z;
    const int hh    = blockIdx.y;
    const int qbase = blockIdx.x * 64;
    const int r4    = (tid >> 4) * 4;
    const int c4    = (tid & 15) * 4;
    const size_t rs = 3 * DD;

    const float* qp = qkv + ((size_t)b * TT + qbase) * rs + hh * DK;
#pragma unroll
    for (int it = 0; it < 4; it++) {
        int s  = tid + it * 256;
        int qq = s >> 4;
        int dq = (s & 15) * 4;
        float4 v = *(const float4*)(qp + (size_t)qq * rs + dq);
        QsT[(dq + 0) * PAD + qq] = v.x;
        QsT[(dq + 1) * PAD + qq] = v.y;
        QsT[(dq + 2) * PAD + qq] = v.z;
        QsT[(dq + 3) * PAD + qq] = v.w;
    }

    float acc[4][4];
    float m_run[4], l_run[4];
#pragma unroll
    for (int i = 0; i < 4; i++) {
        m_run[i] = -INFINITY; l_run[i] = 0.f;
#pragma unroll
        for (int j = 0; j < 4; j++) acc[i][j] = 0.f;
    }

    const int ntiles = blockIdx.x + 1;
    for (int kt = 0; kt < ntiles; kt++) {
        const int j0 = kt * 64;
        __syncthreads();

        const float* kp = qkv + ((size_t)b * TT + j0) * rs + DD + hh * DK;
        const float* vp = kp + DD;
#pragma unroll
        for (int it = 0; it < 4; it++) {
            int s  = tid + it * 256;
            int jj = s >> 4;
            int dq = (s & 15) * 4;
            float4 v = *(const float4*)(kp + (size_t)jj * rs + dq);
            KsT[(dq + 0) * PAD + jj] = v.x;
            KsT[(dq + 1) * PAD + jj] = v.y;
            KsT[(dq + 2) * PAD + jj] = v.z;
            KsT[(dq + 3) * PAD + jj] = v.w;
            float4 w = *(const float4*)(vp + (size_t)jj * rs + dq);
            *(float4*)(Vs + jj * 64 + dq) = w;
        }
        if (tid < 64) padm[tid] = mask[b * TT + j0 + tid];
        __syncthreads();

        float s4[4][4];
#pragma unroll
        for (int i = 0; i < 4; i++)
#pragma unroll
            for (int j = 0; j < 4; j++) s4[i][j] = 0.f;

#pragma unroll 8
        for (int d = 0; d < 64; d++) {
            float qr[4], kr[4];
#pragma unroll
            for (int i = 0; i < 4; i++) qr[i] = QsT[d * PAD + r4 + i];
#pragma unroll
            for (int j = 0; j < 4; j++) kr[j] = KsT[d * PAD + c4 + j];
#pragma unroll
            for (int i = 0; i < 4; i++)
#pragma unroll
                for (int j = 0; j < 4; j++)
                    s4[i][j] += qr[i] * kr[j];
        }

#pragma unroll
        for (int j = 0; j < 4; j++) {
            const int  jg = j0 + c4 + j;
            const bool pm = (padm[c4 + j] != 0);
#pragma unroll
            for (int i = 0; i < 4; i++) {
                const int qg = qbase + r4 + i;
                s4[i][j] = (pm && jg <= qg) ? s4[i][j] * 0.125f : -INFINITY;
            }
        }

#pragma unroll
        for (int i = 0; i < 4; i++) {
            float mloc = fmaxf(fmaxf(s4[i][0], s4[i][1]),
                               fmaxf(s4[i][2], s4[i][3]));
#pragma unroll
            for (int off = 8; off >= 1; off >>= 1)
                mloc = fmaxf(mloc, __shfl_xor_sync(0xffffffffu, mloc, off));

            if (mloc > -INFINITY) {
                float mnew  = fmaxf(m_run[i], mloc);
                float alpha = __expf(m_run[i] - mnew);
                float psum  = 0.f;
#pragma unroll
                for (int j = 0; j < 4; j++) {
                    float p = __expf(s4[i][j] - mnew);
                    s4[i][j] = p;
                    psum += p;
                }
#pragma unroll
                for (int off = 8; off >= 1; off >>= 1)
                    psum += __shfl_xor_sync(0xffffffffu, psum, off);
                l_run[i] = l_run[i] * alpha + psum;
                m_run[i] = mnew;
#pragma unroll
                for (int j = 0; j < 4; j++) acc[i][j] *= alpha;
            } else {
#pragma unroll
                for (int j = 0; j < 4; j++) s4[i][j] = 0.f;
            }
#pragma unroll
            for (int j = 0; j < 4; j++)
                PsT[(c4 + j) * PAD + r4 + i] = s4[i][j];
        }
        __syncthreads();

#pragma unroll 4
        for (int jj = 0; jj < 64; jj++) {
            float pv[4];
#pragma unroll
            for (int i = 0; i < 4; i++) pv[i] = PsT[jj * PAD + r4 + i];
            float4 vf = *(const float4*)(Vs + jj * 64 + c4);
            acc[0][0] += pv[0] * vf.x; acc[0][1] += pv[0] * vf.y;
            acc[0][2] += pv[0] * vf.z; acc[0][3] += pv[0] * vf.w;
            acc[1][0] += pv[1] * vf.x; acc[1][1] += pv[1] * vf.y;
            acc[1][2] += pv[1] * vf.z; acc[1][3] += pv[1] * vf.w;
            acc[2][0] += pv[2] * vf.x; acc[2][1] += pv[2] * vf.y;
            acc[2][2] += pv[2] * vf.z; acc[2][3] += pv[2] * vf.w;
            acc[3][0] += pv[3] * vf.x; acc[3][1] += pv[3] * vf.y;
            acc[3][2] += pv[3] * vf.z; acc[3][3] += pv[3] * vf.w;
        }
    }

#pragma unroll
    for (int i = 0; i < 4; i++) {
        float inv = (l_run[i] > 0.f) ? (1.0f / l_run[i]) : 0.f;
        int t = qbase + r4 + i;
        float4 o;
        o.x = acc[i][0] * inv; o.y = acc[i][1] * inv;
        o.z = acc[i][2] * inv; o.w = acc[i][3] * inv;
        *(float4*)(y + ((size_t)b * TT + t) * DD + hh * DK + c4) = o;
    }
}

// ---------------------------------------------------------------------------
extern "C" void kernel_launch(void* const* d_in, const int* in_sizes, int n_in,
                              void* d_out, int out_size)
{
    const float* x     = (const float*)d_in[0];
    const float* Wqkv  = (const float*)d_in[1];
    const float* bqkv  = (const float*)d_in[2];
    const float* Wproj = (const float*)d_in[3];
    const float* bproj = (const float*)d_in[4];
    const int*   mask  = (const int*)d_in[5];
    float* out = (float*)d_out;

    float *qkvp, *yp;
    __nv_bfloat16 *xpp, *wqp, *ypp, *wpp;
    cudaGetSymbolAddress((void**)&qkvp, g_qkv);
    cudaGetSymbolAddress((void**)&yp,   g_y);
    cudaGetSymbolAddress((void**)&xpp,  g_xp);
    cudaGetSymbolAddress((void**)&wqp,  g_wqkvp);
    cudaGetSymbolAddress((void**)&ypp,  g_yp);
    cudaGetSymbolAddress((void**)&wpp,  g_wprojp);

    cudaFuncSetAttribute(attn_kernel,
                         cudaFuncAttributeMaxDynamicSharedMemorySize, ATT_SMEM);
    cudaFuncSetAttribute(gemm_bf16_mma,
                         cudaFuncAttributeMaxDynamicSharedMemorySize, GEMM_SMEM);

    // split conversions
    split_hilo<<<(MROWS * DD) / 256, 256>>>(x, xpp, MROWS * DD, 0);
    split_hilo<<<(3 * DD * DD) / 256, 256>>>(Wqkv, wqp, 3 * DD * DD, 1);
    split_hilo<<<(DD * DD) / 256, 256>>>(Wproj, wpp, DD * DD, 1);

    // qkv = x @ Wqkv^T + bqkv  (compensated bf16 tensor GEMM, K'=3072)
    gemm_bf16_mma<<<dim3(3 * DD / 128, MROWS / 128), 256, GEMM_SMEM>>>(
        xpp, wqp, bqkv, qkvp, MROWS, 3 * DD, KSPLIT);

    // attention -> g_y
    attn_kernel<<<dim3(TT / 64, HH, BB), 256, ATT_SMEM>>>(qkvp, mask, yp);

    // y split, then out = y @ Wproj^T + bproj
    split_hilo<<<(MROWS * DD) / 256, 256>>>(yp, ypp, MROWS * DD, 0);
    gemm_bf16_mma<<<dim3(DD / 128, MROWS / 128), 256, GEMM_SMEM>>>(
        ypp, wpp, bproj, out, MROWS, DD, KSPLIT);
}

// round 8
// speedup vs baseline: 2.6889x; 2.6710x over previous
#include <cuda_runtime.h>
#include <cuda_bf16.h>
#include <cstdint>
#include <stdint.h>
#include <math.h>

// Problem constants (fixed by the reference)
#define BB 4
#define TT 2048
#define DD 1024
#define HH 16
#define DK 64
#define MROWS (BB * TT)          // 8192
#define KSPLIT (3 * DD)          // 3072 = split-K' for compensated bf16 GEMM

// Scratch (allocation-free rule: __device__ globals)
__device__ float         g_qkv[(size_t)MROWS * 3 * DD];     // [8192][3072] q|k|v fp32
__device__ float         g_y[(size_t)MROWS * DD];           // [8192][1024] fp32
__device__ __nv_bfloat16 g_xp[(size_t)MROWS * KSPLIT];      // x  split  (hi|lo|hi)
__device__ __nv_bfloat16 g_wqkvp[(size_t)(3 * DD) * KSPLIT];// Wqkv split (hi|hi|lo)
__device__ __nv_bfloat16 g_yp[(size_t)MROWS * KSPLIT];      // y  split  (hi|lo|hi)
__device__ __nv_bfloat16 g_wprojp[(size_t)DD * KSPLIT];     // Wproj split (hi|hi|lo)
// attention operand tensors, per (b,h):
__device__ __nv_bfloat16 g_qh[(size_t)BB * HH * TT * DK];   // Q hi  [bh][t][d]
__device__ __nv_bfloat16 g_ql[(size_t)BB * HH * TT * DK];   // Q lo
__device__ __nv_bfloat16 g_kh[(size_t)BB * HH * TT * DK];   // K hi
__device__ __nv_bfloat16 g_kl[(size_t)BB * HH * TT * DK];   // K lo
__device__ __nv_bfloat16 g_vht[(size_t)BB * HH * DK * TT];  // V^T hi [bh][d][t]
__device__ __nv_bfloat16 g_vlt[(size_t)BB * HH * DK * TT];  // V^T lo

// ---------------------------------------------------------------------------
// helpers (all baseline PTX — compiles on compute_103)
// ---------------------------------------------------------------------------
__device__ __forceinline__ uint32_t smem_u32(const void* p) {
    uint32_t a;
    asm("{ .reg .u64 t; cvta.to.shared.u64 t, %1; cvt.u32.u64 %0, t; }"
        : "=r"(a) : "l"(p));
    return a;
}
__device__ __forceinline__ void cp16(uint32_t saddr, const void* gaddr) {
    asm volatile("cp.async.cg.shared.global [%0], [%1], 16;"
                 :: "r"(saddr), "l"(gaddr) : "memory");
}
__device__ __forceinline__ void cp_commit() {
    asm volatile("cp.async.commit_group;" ::: "memory");
}
template <int N>
__device__ __forceinline__ void cp_wait() {
    asm volatile("cp.async.wait_group %0;" :: "n"(N) : "memory");
}
__device__ __forceinline__ void ldsm_x4(uint32_t* r, uint32_t addr) {
    asm volatile("ldmatrix.sync.aligned.m8n8.x4.shared.b16 {%0,%1,%2,%3}, [%4];"
                 : "=r"(r[0]), "=r"(r[1]), "=r"(r[2]), "=r"(r[3]) : "r"(addr));
}
__device__ __forceinline__ void mma_bf16(float* c, const uint32_t* a,
                                         const uint32_t* b) {
    asm volatile(
        "mma.sync.aligned.m16n8k16.row.col.f32.bf16.bf16.f32 "
        "{%0,%1,%2,%3}, {%4,%5,%6,%7}, {%8,%9}, {%0,%1,%2,%3};"
        : "+f"(c[0]), "+f"(c[1]), "+f"(c[2]), "+f"(c[3])
        : "r"(a[0]), "r"(a[1]), "r"(a[2]), "r"(a[3]), "r"(b[0]), "r"(b[1]));
}
__device__ __forceinline__ uint32_t sw128(uint32_t bo) {
    return bo ^ ((bo >> 3) & 0x70);
}
__device__ __forceinline__ uint32_t pack2(float a, float b) {
    __nv_bfloat162 t = __floats2bfloat162_rn(a, b);
    return *(uint32_t*)&t;
}

#define GEMM_SMEM 65536   // 2 x (16KB A + 16KB B)

// ---------------------------------------------------------------------------
// Tensor-core GEMM via mma.sync (unchanged from round 7 — verified)
// ---------------------------------------------------------------------------
__global__ __launch_bounds__(256)
void gemm_bf16_mma(const __nv_bfloat16* __restrict__ A,
                   const __nv_bfloat16* __restrict__ B,
                   const float* __restrict__ bias, float* __restrict__ C,
                   int M, int N, int K)
{
    extern __shared__ char smc[];
    const uint32_t sb = smem_u32(smc);
    const int tid  = threadIdx.x;
    const int wid  = tid >> 5;
    const int lane = tid & 31;
    const int nb   = blockIdx.x * 128;
    const int mb   = blockIdx.y * 128;
    const int mw   = (wid >> 2) * 64;
    const int nw   = (wid & 3) * 32;

    const uint32_t sA = sb;
    const uint32_t sB = sb + 32768;

    float acc[4][4][4];
#pragma unroll
    for (int mt = 0; mt < 4; mt++)
#pragma unroll
        for (int nt = 0; nt < 4; nt++)
#pragma unroll
            for (int q = 0; q < 4; q++) acc[mt][nt][q] = 0.f;

    const int lrow = tid >> 3;
    const int lci  = tid & 7;
    const uint32_t lsw = sw128((uint32_t)(lrow * 128 + lci * 16));

    const int nch = K >> 6;
    {
        const __nv_bfloat16* Ap = A + (size_t)mb * K;
        const __nv_bfloat16* Bp = B + (size_t)nb * K;
#pragma unroll
        for (int i = 0; i < 4; i++) {
            const uint32_t so = lsw + i * 4096;
            cp16(sA + so, Ap + (size_t)(lrow + i * 32) * K + lci * 8);
            cp16(sB + so, Bp + (size_t)(lrow + i * 32) * K + lci * 8);
        }
        cp_commit();
    }

    for (int c = 0; c < nch; c++) {
        const int s = c & 1;
        if (c + 1 < nch) {
            const int k0 = (c + 1) << 6;
            const __nv_bfloat16* Ap = A + (size_t)mb * K + k0;
            const __nv_bfloat16* Bp = B + (size_t)nb * K + k0;
            const uint32_t sbuf = (s ^ 1) * 16384;
#pragma unroll
            for (int i = 0; i < 4; i++) {
                const uint32_t so = sbuf + lsw + i * 4096;
                cp16(sA + so, Ap + (size_t)(lrow + i * 32) * K + lci * 8);
                cp16(sB + so, Bp + (size_t)(lrow + i * 32) * K + lci * 8);
            }
            cp_commit();
            cp_wait<1>();
        } else {
            cp_wait<0>();
        }
        __syncthreads();

        const uint32_t baseA = sA + s * 16384;
        const uint32_t baseB = sB + s * 16384;
#pragma unroll
        for (int ks = 0; ks < 4; ks++) {
            uint32_t af[4][4];
#pragma unroll
            for (int mt = 0; mt < 4; mt++) {
                const int row = mw + mt * 16 + (lane & 15);
                const uint32_t bo =
                    (uint32_t)(row * 128 + ks * 32 + ((lane >> 4) & 1) * 16);
                ldsm_x4(af[mt], baseA + sw128(bo));
            }
            uint32_t bf[4][2];
#pragma unroll
            for (int nt2 = 0; nt2 < 2; nt2++) {
                const int row = nw + nt2 * 16 + ((lane >> 4) << 3) + (lane & 7);
                const uint32_t bo =
                    (uint32_t)(row * 128 + ks * 32 + ((lane >> 3) & 1) * 16);
                uint32_t t[4];
                ldsm_x4(t, baseB + sw128(bo));
                bf[nt2 * 2 + 0][0] = t[0]; bf[nt2 * 2 + 0][1] = t[1];
                bf[nt2 * 2 + 1][0] = t[2]; bf[nt2 * 2 + 1][1] = t[3];
            }
#pragma unroll
            for (int mt = 0; mt < 4; mt++)
#pragma unroll
                for (int nt = 0; nt < 4; nt++)
                    mma_bf16(acc[mt][nt], af[mt], bf[nt]);
        }
        __syncthreads();
    }

    const int r0 = mb + mw + (lane >> 2);
    const int c0 = nb + nw + (lane & 3) * 2;
#pragma unroll
    for (int mt = 0; mt < 4; mt++) {
#pragma unroll
        for (int nt = 0; nt < 4; nt++) {
            const int col = c0 + nt * 8;
            const float bx = bias[col], by = bias[col + 1];
            float2 v0 = make_float2(acc[mt][nt][0] + bx, acc[mt][nt][1] + by);
            float2 v1 = make_float2(acc[mt][nt][2] + bx, acc[mt][nt][3] + by);
            *(float2*)(C + (size_t)(r0 + mt * 16) * N + col)     = v0;
            *(float2*)(C + (size_t)(r0 + mt * 16 + 8) * N + col) = v1;
        }
    }
}

// ---------------------------------------------------------------------------
// Split fp32 -> compensated bf16 triple along K (for the two big GEMMs).
// ---------------------------------------------------------------------------
__global__ __launch_bounds__(256)
void split_hilo(const float* __restrict__ in, __nv_bfloat16* __restrict__ out,
                int total, int type)
{
    int idx = blockIdx.x * 256 + threadIdx.x;
    if (idx >= total) return;
    const int r = idx >> 10;
    const int k = idx & 1023;
    const float x = in[idx];
    const __nv_bfloat16 h = __float2bfloat16(x);
    const __nv_bfloat16 l = __float2bfloat16(x - __bfloat162float(h));
    const size_t o = (size_t)r * KSPLIT + k;
    if (type == 0) { out[o] = h; out[o + 1024] = l; out[o + 2048] = h; }
    else           { out[o] = h; out[o + 1024] = h; out[o + 2048] = l; }
}

// ---------------------------------------------------------------------------
// Q/K split into per-(b,h) hi/lo bf16 tensors [bh][t][64]
// ---------------------------------------------------------------------------
__global__ __launch_bounds__(256)
void qk_split(const float* __restrict__ qkv,
              __nv_bfloat16* __restrict__ qh, __nv_bfloat16* __restrict__ ql,
              __nv_bfloat16* __restrict__ kh, __nv_bfloat16* __restrict__ kl)
{
    const int idx = blockIdx.x * 256 + threadIdx.x;   // 0 .. MROWS*1024
    const int bt = idx >> 10;
    const int hd = idx & 1023;
    const int h  = hd >> 6, d = hd & 63;
    const int b  = bt >> 11, t = bt & 2047;
    const float qv = qkv[(size_t)bt * 3072 + hd];
    const float kv = qkv[(size_t)bt * 3072 + 1024 + hd];
    const size_t o = (((size_t)(b * HH + h) * TT) + t) * DK + d;
    __nv_bfloat16 h1 = __float2bfloat16(qv);
    qh[o] = h1; ql[o] = __float2bfloat16(qv - __bfloat162float(h1));
    __nv_bfloat16 h2 = __float2bfloat16(kv);
    kh[o] = h2; kl[o] = __float2bfloat16(kv - __bfloat162float(h2));
}

// ---------------------------------------------------------------------------
// V transpose + split: [bh][d][t] hi/lo.  Block = (ttile 128, h, b).
// ---------------------------------------------------------------------------
__global__ __launch_bounds__(256)
void v_split(const float* __restrict__ qkv,
             __nv_bfloat16* __restrict__ vht, __nv_bfloat16* __restrict__ vlt)
{
    __shared__ float tile[128][65];
    const int tid = threadIdx.x;
    const int t0  = blockIdx.x * 128;
    const int h   = blockIdx.y;
    const int b   = blockIdx.z;
    const int bh  = b * HH + h;

#pragma unroll
    for (int i = 0; i < 8; i++) {
        const int s   = tid + i * 256;     // 2048 float4 slots
        const int row = s >> 4;
        const int c4  = (s & 15) * 4;
        float4 v = *(const float4*)(qkv + ((size_t)(b * TT) + t0 + row) * 3072 +
                                    2048 + h * DK + c4);
        tile[row][c4 + 0] = v.x; tile[row][c4 + 1] = v.y;
        tile[row][c4 + 2] = v.z; tile[row][c4 + 3] = v.w;
    }
    __syncthreads();

    const int wid  = tid >> 5;
    const int lane = tid & 31;
#pragma unroll
    for (int r = 0; r < 8; r++) {
        const int d = wid * 8 + r;
        uint32_t* oh = (uint32_t*)(vht + ((size_t)bh * DK + d) * TT + t0);
        uint32_t* ol = (uint32_t*)(vlt + ((size_t)bh * DK + d) * TT + t0);
#pragma unroll
        for (int it = 0; it < 2; it++) {
            const int tt = (lane + it * 32) * 2;
            const float v0 = tile[tt][d], v1 = tile[tt + 1][d];
            const __nv_bfloat16 h0 = __float2bfloat16(v0);
            const __nv_bfloat16 h1 = __float2bfloat16(v1);
            const float l0 = v0 - __bfloat162float(h0);
            const float l1 = v1 - __bfloat162float(h1);
            oh[lane + it * 32] = pack2(__bfloat162float(h0), __bfloat162float(h1));
            ol[lane + it * 32] = pack2(l0, l1);
        }
    }
}

// ---------------------------------------------------------------------------
// Flash attention on tensor cores (compensated bf16).
// Block: 128 queries x one (b,h). 256 threads = 8 warps; warp w owns query
// rows [w*16, w*16+16). Key tiles of 64. smem tiles are 128B-row, sw128.
// ---------------------------------------------------------------------------
#define SQHI 0
#define SQLO 16384
#define SKHI 32768
#define SKLO 40960
#define SVHI 49152
#define SVLO 57344
#define SPHI 65536
#define SPLO 81920
#define SPAD 98304
#define ATT2_SMEM (98304 + 256)

__global__ __launch_bounds__(256)
void attn_mma(const __nv_bfloat16* __restrict__ qh,
              const __nv_bfloat16* __restrict__ ql,
              const __nv_bfloat16* __restrict__ kh,
              const __nv_bfloat16* __restrict__ kl,
              const __nv_bfloat16* __restrict__ vht,
              const __nv_bfloat16* __restrict__ vlt,
              const int* __restrict__ mask, float* __restrict__ y)
{
    extern __shared__ char smc[];
    const uint32_t sb = smem_u32(smc);
    int* padm = (int*)(smc + SPAD);

    const int tid  = threadIdx.x;
    const int wid  = tid >> 5;
    const int lane = tid & 31;
    const int bx   = gridDim.x - 1 - blockIdx.x;   // heavy blocks first
    const int b    = blockIdx.z;
    const int hh   = blockIdx.y;
    const int bh   = b * HH + hh;
    const int qb   = bx * 128;

    // ---- load Q (hi & lo), 128 rows x 128B each ----
    {
        const __nv_bfloat16* qhp = qh + ((size_t)bh * TT + qb) * DK;
        const __nv_bfloat16* qlp = ql + ((size_t)bh * TT + qb) * DK;
#pragma unroll
        for (int i = 0; i < 4; i++) {
            const int s   = tid + i * 256;     // 1024 slots
            const int row = s >> 3;
            const int ci  = s & 7;
            const uint32_t sw = sw128((uint32_t)(row * 128 + ci * 16));
            cp16(sb + SQHI + sw, qhp + (size_t)row * DK + ci * 8);
            cp16(sb + SQLO + sw, qlp + (size_t)row * DK + ci * 8);
        }
        cp_commit();
    }

    float acc[8][4];
#pragma unroll
    for (int nt = 0; nt < 8; nt++)
#pragma unroll
        for (int q = 0; q < 4; q++) acc[nt][q] = 0.f;
    float m0 = -INFINITY, m1 = -INFINITY, l0 = 0.f, l1 = 0.f;

    const int r0g = qb + wid * 16 + (lane >> 2);   // global q row (low)
    const int r1g = r0g + 8;                       // global q row (high)

    const int ntiles = 2 * bx + 2;
    for (int kt = 0; kt < ntiles; kt++) {
        const int j0 = kt * 64;
        __syncthreads();   // prior tile's smem reads complete

        // ---- load K hi/lo [64][128B] and V^T hi/lo [64][128B] ----
        {
            const __nv_bfloat16* khp = kh + ((size_t)bh * TT + j0) * DK;
            const __nv_bfloat16* klp = kl + ((size_t)bh * TT + j0) * DK;
            const __nv_bfloat16* vhp = vht + (size_t)bh * DK * TT + j0;
            const __nv_bfloat16* vlp = vlt + (size_t)bh * DK * TT + j0;
#pragma unroll
            for (int i = 0; i < 2; i++) {
                const int s   = tid + i * 256;    // 512 slots
                const int row = s >> 3;
                const int ci  = s & 7;
                const uint32_t sw = sw128((uint32_t)(row * 128 + ci * 16));
                cp16(sb + SKHI + sw, khp + (size_t)row * DK + ci * 8);
                cp16(sb + SKLO + sw, klp + (size_t)row * DK + ci * 8);
                cp16(sb + SVHI + sw, vhp + (size_t)row * TT + ci * 8);
                cp16(sb + SVLO + sw, vlp + (size_t)row * TT + ci * 8);
            }
            if (tid < 64) padm[tid] = mask[b * TT + j0 + tid];
            cp_commit();
            cp_wait<0>();
            __syncthreads();
        }

        // ---- S = Qhi*Khi + Qlo*Khi + Qhi*Klo  (128x64, fp32 acc) ----
        float s4[8][4];
#pragma unroll
        for (int nt = 0; nt < 8; nt++)
#pragma unroll
            for (int q = 0; q < 4; q++) s4[nt][q] = 0.f;

#pragma unroll
        for (int seg = 0; seg < 3; seg++) {
            const uint32_t Ab = sb + (seg == 1 ? SQLO : SQHI);
            const uint32_t Bb = sb + (seg == 2 ? SKLO : SKHI);
#pragma unroll
            for (int ks = 0; ks < 4; ks++) {
                uint32_t af[4];
                {
                    const int row = wid * 16 + (lane & 15);
                    const uint32_t bo =
                        (uint32_t)(row * 128 + ks * 32 + ((lane >> 4) & 1) * 16);
                    ldsm_x4(af, Ab + sw128(bo));
                }
#pragma unroll
                for (int nt2 = 0; nt2 < 4; nt2++) {
                    const int row = nt2 * 16 + ((lane >> 4) << 3) + (lane & 7);
                    const uint32_t bo =
                        (uint32_t)(row * 128 + ks * 32 + ((lane >> 3) & 1) * 16);
                    uint32_t t[4];
                    ldsm_x4(t, Bb + sw128(bo));
                    mma_bf16(s4[nt2 * 2 + 0], af, t);
                    mma_bf16(s4[nt2 * 2 + 1], af, t + 2);
                }
            }
        }

        // ---- mask + scale ----
#pragma unroll
        for (int nt = 0; nt < 8; nt++) {
            const int c0 = nt * 8 + (lane & 3) * 2;
            const bool p0 = padm[c0] != 0, p1 = padm[c0 + 1] != 0;
            const int jg0 = j0 + c0, jg1 = jg0 + 1;
            s4[nt][0] = (p0 && jg0 <= r0g) ? s4[nt][0] * 0.125f : -INFINITY;
            s4[nt][1] = (p1 && jg1 <= r0g) ? s4[nt][1] * 0.125f : -INFINITY;
            s4[nt][2] = (p0 && jg0 <= r1g) ? s4[nt][2] * 0.125f : -INFINITY;
            s4[nt][3] = (p1 && jg1 <= r1g) ? s4[nt][3] * 0.125f : -INFINITY;
        }

        // ---- online softmax (rows live in quads: shfl over lane^1, lane^2) ----
        float mx0 = -INFINITY, mx1 = -INFINITY;
#pragma unroll
        for (int nt = 0; nt < 8; nt++) {
            mx0 = fmaxf(mx0, fmaxf(s4[nt][0], s4[nt][1]));
            mx1 = fmaxf(mx1, fmaxf(s4[nt][2], s4[nt][3]));
        }
        mx0 = fmaxf(mx0, __shfl_xor_sync(0xffffffffu, mx0, 1));
        mx0 = fmaxf(mx0, __shfl_xor_sync(0xffffffffu, mx0, 2));
        mx1 = fmaxf(mx1, __shfl_xor_sync(0xffffffffu, mx1, 1));
        mx1 = fmaxf(mx1, __shfl_xor_sync(0xffffffffu, mx1, 2));

        float a0 = 1.f, a1 = 1.f;
        if (mx0 > -INFINITY) {
            const float mn = fmaxf(m0, mx0);
            a0 = __expf(m0 - mn);           // exp(-inf)=0 on first tile
            m0 = mn;
        }
        if (mx1 > -INFINITY) {
            const float mn = fmaxf(m1, mx1);
            a1 = __expf(m1 - mn);
            m1 = mn;
        }
        const float mm0 = (m0 == -INFINITY) ? 0.f : m0;
        const float mm1 = (m1 == -INFINITY) ? 0.f : m1;

        // ---- p = exp(s-m), partial sums, hi/lo -> smem P tiles ----
        const int pr0 = wid * 16 + (lane >> 2);
        const uint32_t pcolb = (uint32_t)((lane & 3) * 4);   // byte offset of col pair
        float sum0 = 0.f, sum1 = 0.f;
#pragma unroll
        for (int nt = 0; nt < 8; nt++) {
            const float p00 = __expf(s4[nt][0] - mm0);
            const float p01 = __expf(s4[nt][1] - mm0);
            const float p10 = __expf(s4[nt][2] - mm1);
            const float p11 = __expf(s4[nt][3] - mm1);
            sum0 += p00 + p01;
            sum1 += p10 + p11;
            // hi parts
            const float h00 = __bfloat162float(__float2bfloat16(p00));
            const float h01 = __bfloat162float(__float2bfloat16(p01));
            const float h10 = __bfloat162float(__float2bfloat16(p10));
            const float h11 = __bfloat162float(__float2bfloat16(p11));
            const uint32_t bo0 = (uint32_t)(pr0 * 128 + nt * 16) + pcolb;
            const uint32_t bo1 = bo0 + 8 * 128;
            *(uint32_t*)(smc + SPHI + sw128(bo0)) = pack2(h00, h01);
            *(uint32_t*)(smc + SPHI + sw128(bo1)) = pack2(h10, h11);
            *(uint32_t*)(smc + SPLO + sw128(bo0)) = pack2(p00 - h00, p01 - h01);
            *(uint32_t*)(smc + SPLO + sw128(bo1)) = pack2(p10 - h10, p11 - h11);
        }
        sum0 += __shfl_xor_sync(0xffffffffu, sum0, 1);
        sum0 += __shfl_xor_sync(0xffffffffu, sum0, 2);
        sum1 += __shfl_xor_sync(0xffffffffu, sum1, 1);
        sum1 += __shfl_xor_sync(0xffffffffu, sum1, 2);
        l0 = l0 * a0 + sum0;
        l1 = l1 * a1 + sum1;

        // rescale running O
#pragma unroll
        for (int nt = 0; nt < 8; nt++) {
            acc[nt][0] *= a0; acc[nt][1] *= a0;
            acc[nt][2] *= a1; acc[nt][3] *= a1;
        }
        __syncwarp();   // P stores visible to this warp's ldmatrix

        // ---- O += Phi*Vhi + Plo*Vhi + Phi*Vlo ----
#pragma unroll
        for (int seg = 0; seg < 3; seg++) {
            const uint32_t Ab = sb + (seg == 1 ? SPLO : SPHI);
            const uint32_t Bb = sb + (seg == 2 ? SVLO : SVHI);
#pragma unroll
            for (int ks = 0; ks < 4; ks++) {
                uint32_t af[4];
                {
                    const int row = wid * 16 + (lane & 15);
                    const uint32_t bo =
                        (uint32_t)(row * 128 + ks * 32 + ((lane >> 4) & 1) * 16);
                    ldsm_x4(af, Ab + sw128(bo));
                }
#pragma unroll
                for (int nt2 = 0; nt2 < 4; nt2++) {
                    const int row = nt2 * 16 + ((lane >> 4) << 3) + (lane & 7);
                    const uint32_t bo =
                        (uint32_t)(row * 128 + ks * 32 + ((lane >> 3) & 1) * 16);
                    uint32_t t[4];
                    ldsm_x4(t, Bb + sw128(bo));
                    mma_bf16(acc[nt2 * 2 + 0], af, t);
                    mma_bf16(acc[nt2 * 2 + 1], af, t + 2);
                }
            }
        }
    }

    // ---- epilogue: y[b][t][h*64+d] = O / l ----
    const float inv0 = (l0 > 0.f) ? (1.f / l0) : 0.f;
    const float inv1 = (l1 > 0.f) ? (1.f / l1) : 0.f;
#pragma unroll
    for (int nt = 0; nt < 8; nt++) {
        const int col = hh * DK + nt * 8 + (lane & 3) * 2;
        *(float2*)(y + ((size_t)b * TT + r0g) * DD + col) =
            make_float2(acc[nt][0] * inv0, acc[nt][1] * inv0);
        *(float2*)(y + ((size_t)b * TT + r1g) * DD + col) =
            make_float2(acc[nt][2] * inv1, acc[nt][3] * inv1);
    }
}

// ---------------------------------------------------------------------------
extern "C" void kernel_launch(void* const* d_in, const int* in_sizes, int n_in,
                              void* d_out, int out_size)
{
    const float* x     = (const float*)d_in[0];
    const float* Wqkv  = (const float*)d_in[1];
    const float* bqkv  = (const float*)d_in[2];
    const float* Wproj = (const float*)d_in[3];
    const float* bproj = (const float*)d_in[4];
    const int*   mask  = (const int*)d_in[5];
    float* out = (float*)d_out;

    float *qkvp, *yp;
    __nv_bfloat16 *xpp, *wqp, *ypp, *wpp;
    __nv_bfloat16 *qhp, *qlp, *khp, *klp, *vhp, *vlp;
    cudaGetSymbolAddress((void**)&qkvp, g_qkv);
    cudaGetSymbolAddress((void**)&yp,   g_y);
    cudaGetSymbolAddress((void**)&xpp,  g_xp);
    cudaGetSymbolAddress((void**)&wqp,  g_wqkvp);
    cudaGetSymbolAddress((void**)&ypp,  g_yp);
    cudaGetSymbolAddress((void**)&wpp,  g_wprojp);
    cudaGetSymbolAddress((void**)&qhp,  g_qh);
    cudaGetSymbolAddress((void**)&qlp,  g_ql);
    cudaGetSymbolAddress((void**)&khp,  g_kh);
    cudaGetSymbolAddress((void**)&klp,  g_kl);
    cudaGetSymbolAddress((void**)&vhp,  g_vht);
    cudaGetSymbolAddress((void**)&vlp,  g_vlt);

    cudaFuncSetAttribute(gemm_bf16_mma,
                         cudaFuncAttributeMaxDynamicSharedMemorySize, GEMM_SMEM);
    cudaFuncSetAttribute(attn_mma,
                         cudaFuncAttributeMaxDynamicSharedMemorySize, ATT2_SMEM);

    // input splits for qkv GEMM
    split_hilo<<<(MROWS * DD) / 256, 256>>>(x, xpp, MROWS * DD, 0);
    split_hilo<<<(3 * DD * DD) / 256, 256>>>(Wqkv, wqp, 3 * DD * DD, 1);
    split_hilo<<<(DD * DD) / 256, 256>>>(Wproj, wpp, DD * DD, 1);

    // qkv = x @ Wqkv^T + bqkv
    gemm_bf16_mma<<<dim3(3 * DD / 128, MROWS / 128), 256, GEMM_SMEM>>>(
        xpp, wqp, bqkv, qkvp, MROWS, 3 * DD, KSPLIT);

    // attention operand prep
    qk_split<<<(MROWS * DD) / 256, 256>>>(qkvp, qhp, qlp, khp, klp);
    v_split<<<dim3(TT / 128, HH, BB), 256>>>(qkvp, vhp, vlp);

    // attention -> g_y
    attn_mma<<<dim3(TT / 128, HH, BB), 256, ATT2_SMEM>>>(
        qhp, qlp, khp, klp, vhp, vlp, mask, yp);

    // y split, then out = y @ Wproj^T + bproj
    split_hilo<<<(MROWS * DD) / 256, 256>>>(yp, ypp, MROWS * DD, 0);
    gemm_bf16_mma<<<dim3(DD / 128, MROWS / 128), 256, GEMM_SMEM>>>(
        ypp, wpp, bproj, out, MROWS, DD, KSPLIT);
}